// round 13
// baseline (speedup 1.0000x reference)
#include <cuda_runtime.h>
#include <cuda_bf16.h>
#include <cstdint>

#define B_   8
#define C_   512
#define H_   14
#define W_   14
#define P_   196
#define HS_  1024
#define KC_  144
#define KP_  432      // 3 exact sections of 144 (no padding; 144 % 16 == 0)
#define NBO  72

__device__ float g_q1[B_ * P_ * HS_];
__device__ float g_q2[B_ * P_ * HS_];
__device__ __align__(16) __nv_bfloat16 g_Aexp[B_  * HS_ * KP_];
__device__ __align__(16) __nv_bfloat16 g_Bexp[NBO * HS_ * KP_];

// ---- packed f32x2 ----
__device__ __forceinline__ unsigned long long pack2(float lo, float hi) {
    unsigned long long r; asm("mov.b64 %0, {%1, %2};" : "=l"(r) : "f"(lo), "f"(hi)); return r;
}
__device__ __forceinline__ void unpack2(unsigned long long v, float& lo, float& hi) {
    asm("mov.b64 {%0, %1}, %2;" : "=f"(lo), "=f"(hi) : "l"(v));
}
__device__ __forceinline__ void fma2(unsigned long long& d, unsigned long long a, unsigned long long b) {
    asm("fma.rn.f32x2 %0, %1, %2, %0;" : "+l"(d) : "l"(a), "l"(b));
}

// ---- smem / async-copy / mma helpers ----
__device__ __forceinline__ uint32_t smem_u32(const void* p) {
    uint32_t a; asm("{ .reg .u64 t; cvta.to.shared.u64 t, %1; cvt.u32.u64 %0, t; }" : "=r"(a) : "l"(p)); return a;
}
#define CP_ASYNC16(dst, src) \
    asm volatile("cp.async.cg.shared.global [%0], [%1], 16;" :: "r"(dst), "l"(src) : "memory")
#define CP_COMMIT() asm volatile("cp.async.commit_group;" ::: "memory")
#define CP_WAIT1()  asm volatile("cp.async.wait_group 1;" ::: "memory")
#define CP_WAIT0()  asm volatile("cp.async.wait_group 0;" ::: "memory")

__device__ __forceinline__ void ldsm_x4(uint32_t& r0, uint32_t& r1, uint32_t& r2, uint32_t& r3, uint32_t a) {
    asm volatile("ldmatrix.sync.aligned.m8n8.x4.shared.b16 {%0,%1,%2,%3}, [%4];"
                 : "=r"(r0), "=r"(r1), "=r"(r2), "=r"(r3) : "r"(a));
}
__device__ __forceinline__ void mma16816(float* d, const uint32_t* a, uint32_t b0, uint32_t b1) {
    asm volatile("mma.sync.aligned.m16n8k16.row.col.f32.bf16.bf16.f32 "
                 "{%0,%1,%2,%3}, {%4,%5,%6,%7}, {%8,%9}, {%0,%1,%2,%3};"
                 : "+f"(d[0]), "+f"(d[1]), "+f"(d[2]), "+f"(d[3])
                 : "r"(a[0]), "r"(a[1]), "r"(a[2]), "r"(a[3]), "r"(b0), "r"(b1));
}

// ===================== Phase 1: projections (vector-LDS rewrite) =====================
// CTA: 32 p x 128 h. Thread tile: 8p x 2h. Inner loop per k:
//   2x LDS.128 (A pairs, directly fma2-ready) + 2 scalar LDS (w) + 8 fma2.
__global__ __launch_bounds__(256) void proj_kernel(
    const float* __restrict__ x,
    const float* __restrict__ w1, const float* __restrict__ b1,
    const float* __restrict__ w2, const float* __restrict__ b2)
{
    const int nt = blockIdx.x, mt = blockIdx.y;
    const int b = blockIdx.z >> 1, sel = blockIdx.z & 1;
    const float* w = sel ? w2 : w1;
    const float* bias = sel ? b2 : b1;
    float* q = sel ? g_q2 : g_q1;

    __shared__ __align__(16) float As[32][36];   // [c'][p'] row 144B (16B-mult)
    __shared__ float Ws[32][129];                // [c'][h'] stride 129 -> conflict-free stores
    const int tid = threadIdx.x;
    const int px = tid & 3, hy = tid >> 2;       // p-octet, h-pair
    const int p0 = mt * 32, h0 = nt * 128;
    const int hh2 = hy * 2;
    const float* xb = x + (size_t)b * C_ * P_;

    unsigned long long acc[8];                   // [p-octet elem] = (h_lo, h_hi)... layout: acc[e] h-pair for p e
#pragma unroll
    for (int e = 0; e < 8; e++) acc[e] = 0ull;

    for (int c0 = 0; c0 < C_; c0 += 32) {
        __syncthreads();
#pragma unroll
        for (int r = 0; r < 4; r++) {
            int i = tid + 256 * r, cc = i >> 5, pp = i & 31, p = p0 + pp;
            As[cc][pp] = (p < P_) ? xb[(size_t)(c0 + cc) * P_ + p] : 0.f;
        }
#pragma unroll
        for (int r = 0; r < 16; r++) {
            int i = tid + 256 * r, cc = i & 31, hh = i >> 5;
            Ws[cc][hh] = w[(size_t)(h0 + hh) * C_ + c0 + cc];
        }
        __syncthreads();
#pragma unroll
        for (int kk = 0; kk < 32; kk++) {
            // A: 8 p values as 4 packed pairs (2x LDS.128)
            ulonglong2 av0 = *(ulonglong2*)&As[kk][px * 8];
            ulonglong2 av1 = *(ulonglong2*)&As[kk][px * 8 + 4];
            float wl = Ws[kk][hh2], wh = Ws[kk][hh2 + 1];
            unsigned long long WL = pack2(wl, wl), WH = pack2(wh, wh);
            // acc[e] = h-major: acc[0..3] for h_lo over p-pairs, acc[4..7] for h_hi
            fma2(acc[0], av0.x, WL); fma2(acc[1], av0.y, WL);
            fma2(acc[2], av1.x, WL); fma2(acc[3], av1.y, WL);
            fma2(acc[4], av0.x, WH); fma2(acc[5], av0.y, WH);
            fma2(acc[6], av1.x, WH); fma2(acc[7], av1.y, WH);
        }
    }

    // epilogue: acc[t] = (p = 2t, 2t+1) for h_lo; acc[4+t] for h_hi
    const float2 bias2 = *(const float2*)&bias[h0 + hh2];
#pragma unroll
    for (int t = 0; t < 4; t++) {
        float l0, l1, hA, hB;
        unpack2(acc[t], l0, l1);
        unpack2(acc[4 + t], hA, hB);
        int pA = p0 + px * 8 + t * 2, pB = pA + 1;
        if (pA < P_) *(float2*)&q[((size_t)b * P_ + pA) * HS_ + h0 + hh2] = make_float2(l0 + bias2.x, hA + bias2.y);
        if (pB < P_) *(float2*)&q[((size_t)b * P_ + pB) * HS_ + h0 + hh2] = make_float2(l1 + bias2.x, hB + bias2.y);
    }
}

// ===================== Phase 1.5: bf16 split + K-major expand =====================
__global__ __launch_bounds__(128) void convert_kernel()
{
    __shared__ float tile[KC_][65];
    const int jt = blockIdx.x, z = blockIdx.y, tid = threadIdx.x;
    const float* src; int dy, dx, losec; __nv_bfloat16* dst;
    if (z < NBO) {
        int b = z / 9, o = z % 9;
        dy = o / 3 - 1; dx = o % 3 - 1; losec = 1;
        src = g_q2 + (size_t)b * P_ * HS_;
        dst = g_Bexp + (size_t)z * HS_ * KP_;
    } else {
        int b = z - NBO; dy = 0; dx = 0; losec = 2;
        src = g_q1 + (size_t)b * P_ * HS_;
        dst = g_Aexp + (size_t)b * HS_ * KP_;
    }
    const int j0 = jt * 64;
#pragma unroll
    for (int t = 0; t < 72; t++) {
        int idx = t * 128 + tid, kk = idx >> 6, jj = idx & 63;
        int ky = kk / 12, kx = kk - ky * 12;
        int pos = (ky + 1 + dy) * W_ + (kx + 1 + dx);
        tile[kk][jj] = src[(size_t)pos * HS_ + j0 + jj];
    }
    __syncthreads();
    const int j = tid >> 1, half = tid & 1;
    __nv_bfloat16* drow = dst + (size_t)(j0 + j) * KP_;
#pragma unroll
    for (int u = 0; u < 27; u++) {
        int kp0 = half * 216 + u * 8;
        unsigned short wv[8];
#pragma unroll
        for (int e = 0; e < 8; e++) {
            int kp = kp0 + e, s = kp / 144, kk = kp - s * 144;
            float v = tile[kk][j];
            __nv_bfloat16 h = __float2bfloat16(v);
            __nv_bfloat16 r = (s == losec) ? __float2bfloat16(v - __bfloat162float(h)) : h;
            wv[e] = *reinterpret_cast<unsigned short*>(&r);
        }
        *(uint4*)(drow + kp0) = *(uint4*)wv;
    }
}

// ===================== Phase 2: mma.sync bf16 GEMM (R6 shape, K'=432) =====================
// CTA 128i x 128j, 8 warps (2x4), warp tile 64x32. K' in 9 chunks of 48
// (96B per 128B smem row slot, ch 0..5). cp.async double buffer.
#define GEMM_SMEM 65536

__device__ __forceinline__ void load_chunk(
    const __nv_bfloat16* __restrict__ Ab, const __nv_bfloat16* __restrict__ Bb,
    uint32_t sa, int c, int buf, int tid)
{
    const uint32_t abase = sa + buf * 16384;
    const uint32_t bbase = sa + 32768 + buf * 16384;
    const int row = tid >> 1, half = tid & 1;
    const char* sA = (const char*)(Ab + (size_t)row * KP_ + c * 48);
    const char* sB = (const char*)(Bb + (size_t)row * KP_ + c * 48);
    const int rw = row & 7;
#pragma unroll
    for (int e = 0; e < 3; e++) {
        int ch = half * 3 + e;
        CP_ASYNC16(abase + row * 128 + ((ch ^ rw) << 4), sA + ch * 16);
    }
#pragma unroll
    for (int e = 0; e < 3; e++) {
        int ch = half * 3 + e;
        CP_ASYNC16(bbase + row * 128 + ((ch ^ rw) << 4), sB + ch * 16);
    }
}

__global__ __launch_bounds__(256, 1) void gemm_kernel(float* __restrict__ out)
{
    extern __shared__ __align__(128) char smem[];
    const uint32_t sa = smem_u32(smem);
    const int tid = threadIdx.x, wid = tid >> 5, lane = tid & 31;
    const int jt = blockIdx.x, it = blockIdx.y, bo = blockIdx.z;
    const int i0 = it * 128, j0 = jt * 128;
    const int wm = wid >> 2, wn = wid & 3;

    const __nv_bfloat16* Ab = g_Aexp + ((size_t)(bo / 9)) * HS_ * KP_ + (size_t)i0 * KP_;
    const __nv_bfloat16* Bb = g_Bexp + (size_t)bo * HS_ * KP_ + (size_t)j0 * KP_;

    load_chunk(Ab, Bb, sa, 0, 0, tid); CP_COMMIT();
    load_chunk(Ab, Bb, sa, 1, 1, tid); CP_COMMIT();

    float d[4][4][4];
#pragma unroll
    for (int mt = 0; mt < 4; mt++)
#pragma unroll
        for (int nt = 0; nt < 4; nt++)
#pragma unroll
            for (int e = 0; e < 4; e++) d[mt][nt][e] = 0.f;

    const int la_row = (lane & 7) + ((lane >> 3) & 1) * 8;
    const int la_ch  = lane >> 4;
    const int lb_row = (lane & 7) + (lane >> 4) * 8;
    const int lb_ch  = (lane >> 3) & 1;

    for (int c = 0; c < 9; c++) {
        const int buf = c & 1;
        if (c == 8) { CP_WAIT0(); } else { CP_WAIT1(); }
        __syncthreads();
        const uint32_t abase = sa + buf * 16384;
        const uint32_t bbase = sa + 32768 + buf * 16384;
#pragma unroll
        for (int ks = 0; ks < 3; ks++) {
            uint32_t a[4][4];
#pragma unroll
            for (int mt = 0; mt < 4; mt++) {
                int row = wm * 64 + mt * 16 + la_row;
                int ch  = ks * 2 + la_ch;
                ldsm_x4(a[mt][0], a[mt][1], a[mt][2], a[mt][3],
                        abase + row * 128 + ((ch ^ (row & 7)) << 4));
            }
            uint32_t bf[2][4];
#pragma unroll
            for (int np = 0; np < 2; np++) {
                int row = wn * 32 + np * 16 + lb_row;
                int ch  = ks * 2 + lb_ch;
                ldsm_x4(bf[np][0], bf[np][1], bf[np][2], bf[np][3],
                        bbase + row * 128 + ((ch ^ (row & 7)) << 4));
            }
#pragma unroll
            for (int mt = 0; mt < 4; mt++)
#pragma unroll
                for (int nt = 0; nt < 4; nt++)
                    mma16816(d[mt][nt], a[mt], bf[nt >> 1][(nt & 1) * 2], bf[nt >> 1][(nt & 1) * 2 + 1]);
        }
        __syncthreads();
        if (c + 2 < 9) { load_chunk(Ab, Bb, sa, c + 2, buf, tid); CP_COMMIT(); }
    }

    // epilogue: raw write
    float* obase = out + (size_t)bo * HS_ * HS_;
    const int r0 = i0 + wm * 64 + (lane >> 2);
    const int c0 = j0 + wn * 32 + (lane & 3) * 2;
#pragma unroll
    for (int mt = 0; mt < 4; mt++) {
        int row = r0 + mt * 16;
#pragma unroll
        for (int nt = 0; nt < 4; nt++) {
            int col = c0 + nt * 8;
            *(float2*)(obase + (size_t)row * HS_ + col)       = make_float2(d[mt][nt][0], d[mt][nt][1]);
            *(float2*)(obase + (size_t)(row + 8) * HS_ + col) = make_float2(d[mt][nt][2], d[mt][nt][3]);
        }
    }
}

// ===================== Phase 3: row L2-normalize in place =====================
__global__ __launch_bounds__(256) void normalize_kernel(float* __restrict__ out)
{
    const int it = blockIdx.x, bo = blockIdx.y;
    const int wid = threadIdx.x >> 5, lid = threadIdx.x & 31;
#pragma unroll 1
    for (int pass = 0; pass < 16; pass++) {
        int row = it * 128 + pass * 8 + wid;
        float4* p = (float4*)(out + ((size_t)bo * HS_ + row) * HS_);
        float4 v[8]; float s = 0.f;
#pragma unroll
        for (int f = 0; f < 8; f++) {
            v[f] = p[lid + f * 32];
            s += v[f].x * v[f].x + v[f].y * v[f].y + v[f].z * v[f].z + v[f].w * v[f].w;
        }
#pragma unroll
        for (int off = 16; off > 0; off >>= 1) s += __shfl_xor_sync(0xffffffffu, s, off);
        float inv = 1.f / fmaxf(sqrtf(s), 1e-12f);
#pragma unroll
        for (int f = 0; f < 8; f++) {
            v[f].x *= inv; v[f].y *= inv; v[f].z *= inv; v[f].w *= inv;
            p[lid + f * 32] = v[f];
        }
    }
}

extern "C" void kernel_launch(void* const* d_in, const int* in_sizes, int n_in,
                              void* d_out, int out_size)
{
    const float* x  = (const float*)d_in[0];
    const float* w1 = (const float*)d_in[1];
    const float* b1 = (const float*)d_in[2];
    const float* w2 = (const float*)d_in[3];
    const float* b2 = (const float*)d_in[4];
    float* out = (float*)d_out;

    cudaFuncSetAttribute(gemm_kernel, cudaFuncAttributeMaxDynamicSharedMemorySize, GEMM_SMEM);

    proj_kernel<<<dim3(8, 7, 16), 256>>>(x, w1, b1, w2, b2);
    convert_kernel<<<dim3(16, 80), 128>>>();
    gemm_kernel<<<dim3(8, 8, 72), 256, GEMM_SMEM>>>(out);
    normalize_kernel<<<dim3(8, 72), 256>>>(out);
}